// round 15
// baseline (speedup 1.0000x reference)
#include <cuda_runtime.h>
#include <cstdint>

#define NB      8
#define NHEADS  12
#define HH      24
#define SEQ     576
#define DIM     64
#define NPOS    24
#define BATCH   96
#define KPAD    28          // row stride (words): 16B-aligned; frag reads conflict-free

// Scratch: tf32-truncated pe_x_flat / pe_y_flat  [BATCH][SEQ][NPOS]
__device__ __align__(16) float g_Vx[BATCH * SEQ * NPOS];
__device__ __align__(16) float g_Vy[BATCH * SEQ * NPOS];
// Row norms of the truncated vectors: [path][bh*SEQ + row]
__device__ __align__(16) float g_Nrm[2][BATCH * SEQ];

__device__ __forceinline__ float sigmoidf_(float x) {
    return 1.0f / (1.0f + __expf(-x));
}

__device__ __forceinline__ unsigned long long fma2(unsigned long long a,
                                                   unsigned long long b,
                                                   unsigned long long c) {
    unsigned long long d;
    asm("fma.rn.f32x2 %0, %1, %2, %3;" : "=l"(d) : "l"(a), "l"(b), "l"(c));
    return d;
}

__device__ __forceinline__ unsigned long long pack2(float lo, float hi) {
    unsigned long long r;
    asm("mov.b64 %0, {%1, %2};" : "=l"(r) : "f"(lo), "f"(hi));
    return r;
}

__device__ __forceinline__ float fsqrt_approx(float x) {
    float r;
    asm("sqrt.approx.f32 %0, %1;" : "=f"(r) : "f"(x));
    return r;
}

__device__ __forceinline__ uint32_t f2tf32(float v) {
    uint32_t r;
    asm("cvt.rna.tf32.f32 %0, %1;" : "=r"(r) : "f"(v));
    return r;
}

__device__ __forceinline__ void mma_tf32(float* c, const uint32_t* a, uint32_t b0, uint32_t b1) {
    asm volatile(
        "mma.sync.aligned.m16n8k8.row.col.f32.tf32.tf32.f32 "
        "{%0,%1,%2,%3}, {%4,%5,%6,%7}, {%8,%9}, {%0,%1,%2,%3};"
        : "+f"(c[0]), "+f"(c[1]), "+f"(c[2]), "+f"(c[3])
        : "r"(a[0]), "r"(a[1]), "r"(a[2]), "r"(a[3]), "r"(b0), "r"(b1));
}

// ---------------------------------------------------------------------------
// Kernel 1: fused CoPE (R12 form) + tf32 truncation + norm reduce at the tail.
// ---------------------------------------------------------------------------
__global__ void __launch_bounds__(512) cope_kernel(
    const float* __restrict__ query,      // [8,12,576,64]
    const float* __restrict__ attn,       // [8,12,576,576]
    const float* __restrict__ pex,        // [64,24]
    const float* __restrict__ pey)        // [64,24]
{
    __shared__ __align__(16) float q_s[2][HH * 68];
    __shared__ __align__(16) float pe_s[2][DIM * NPOS];
    __shared__ __align__(8)  float li[2][HH * 26];

    int t    = threadIdx.x;
    int path = t >> 8;
    int tp   = t & 255;

    int id   = blockIdx.x;
    int n    = id / 12;
    int m    = id % 12;
    int b_a  = id / 288;
    int hd_a = (id / 24) % 12;
    int r_a  = id % 24;
    int b_q  = n / 24;
    int s_q  = n % 24;

    {
        const float4* pe4 = (const float4*)(path ? pey : pex);
        float4* d4 = (float4*)pe_s[path];
        for (int idx = tp; idx < DIM * NPOS / 4; idx += 256)
            d4[idx] = pe4[idx];
    }

    if (!path) {
        const float4* qb = (const float4*)(query + (((size_t)(b_q * 12 + m)) * SEQ + s_q * 24) * DIM);
        for (int idx = tp; idx < HH * DIM / 4; idx += 256) {
            int rr = idx >> 4, c4 = (idx & 15) * 4;
            *(float4*)&q_s[0][rr * 68 + c4] = qb[idx];
        }
    } else {
        const float* qb = query + (((size_t)(b_q * 12 + m)) * SEQ + s_q) * DIM;
        for (int idx = tp; idx < HH * DIM / 4; idx += 256) {
            int rr = idx >> 4, c4 = (idx & 15) * 4;
            *(float4*)&q_s[1][rr * 68 + c4] = *(const float4*)(qb + (size_t)rr * (24 * DIM) + c4);
        }
    }
    __syncthreads();

    for (int o = t; o < 2 * HH * 12; o += 512) {
        int pa  = (o >= 288) ? 1 : 0;
        int rem = o - pa * 288;
        int j   = rem / 12;
        int pp  = rem - j * 12;
        const float4* qr4 = (const float4*)&q_s[pa][j * 68];
        const float*  pr  = pe_s[pa] + 2 * pp;
        unsigned long long acc = 0ull;
        #pragma unroll
        for (int dq = 0; dq < 16; dq++) {
            float4 q4 = qr4[dq];
            float2 v0 = *(const float2*)(pr + (4 * dq + 0) * NPOS);
            float2 v1 = *(const float2*)(pr + (4 * dq + 1) * NPOS);
            float2 v2 = *(const float2*)(pr + (4 * dq + 2) * NPOS);
            float2 v3 = *(const float2*)(pr + (4 * dq + 3) * NPOS);
            acc = fma2(pack2(q4.x, q4.x), pack2(v0.x, v0.y), acc);
            acc = fma2(pack2(q4.y, q4.y), pack2(v1.x, v1.y), acc);
            acc = fma2(pack2(q4.z, q4.z), pack2(v2.x, v2.y), acc);
            acc = fma2(pack2(q4.w, q4.w), pack2(v3.x, v3.y), acc);
        }
        *(float2*)(&li[pa][j * 26 + 2 * pp]) = *(float2*)&acc;
    }
    __syncthreads();

    int w    = (t >> 5) & 7;
    int lane = t & 31;
    int bh   = b_q * 12 + m;
    for (int j = w; j < HH; j += 8) {
        const float* arow;
        int astride;
        int row;
        if (!path) {
            arow = attn + (((size_t)(b_a * 12 + hd_a)) * SEQ + (size_t)(r_a * 24 + j)) * SEQ
                        + (size_t)(r_a * 24);
            astride = 1;
            row = s_q * 24 + j;
        } else {
            arow = attn + (((size_t)(b_a * 12 + hd_a)) * SEQ + (size_t)(j * 24 + r_a)) * SEQ
                        + (size_t)r_a;
            astride = 24;
            row = j * 24 + s_q;
        }
        float v = 0.0f;
        if (lane < NPOS)
            v = sigmoidf_(arow[lane * astride]);
        #pragma unroll
        for (int d = 1; d < 32; d <<= 1) {
            float tv = __shfl_down_sync(0xffffffffu, v, d);
            if (lane + d < NPOS) v += tv;
        }
        float tval = 0.0f;
        if (lane < NPOS) {
            float pp = fminf(v, (float)(NPOS - 1));
            float pf = floorf(pp);
            int   ifl = (int)pf;
            int   ic  = (int)ceilf(pp);
            float wq  = pp - pf;
            float val = li[path][j * 26 + ic] * wq + li[path][j * 26 + ifl] * (1.0f - wq);
            tval = __uint_as_float(f2tf32(val));      // truncate ONCE, here
            float* dst = (path ? g_Vy : g_Vx) + ((size_t)bh * SEQ + row) * NPOS;
            dst[lane] = tval;
        }
        // norm of the truncated row (lanes >= NPOS contribute 0)
        float sq = tval * tval;
        #pragma unroll
        for (int d = 16; d >= 1; d >>= 1)
            sq += __shfl_down_sync(0xffffffffu, sq, d);
        if (lane == 0)
            g_Nrm[path][bh * SEQ + row] = sq;
    }
}

// ---------------------------------------------------------------------------
// Kernel 2: fused double-cdist + mix via tf32 mma. V already truncated and
// norms precomputed by cope. Load = pure float4 copy; frag loads via hoisted
// base pointers + compile-time immediate offsets (no per-access IMAD).
// ---------------------------------------------------------------------------
union DistSm {
    float V[2][2][64 * KPAD];   // [path][A=0/B=1][row][k]
    float T[64 * 65];
};

__global__ void __launch_bounds__(128) dist_kernel(
    const float* __restrict__ wxp,
    float* __restrict__ out)
{
    __shared__ __align__(16) DistSm sm;
    __shared__ float nrm[2][2][64];

    int bz = blockIdx.y;
    int u = blockIdx.x;
    int ti = 0;
    #pragma unroll 1
    while (u >= (9 - ti)) { u -= (9 - ti); ti++; }
    int tj = ti + u;
    int p0 = ti * 64;
    int q0 = tj * 64;

    int t    = threadIdx.x;     // 0..127
    int w    = t >> 5;          // warp id = m-strip
    int lane = t & 31;

    // ---- Load (pure copy, already tf32-truncated): 1536 float4 tasks ----
    for (int task = t; task < 4 * 384; task += 128) {
        int grp = task / 384;           // pa*2 + ab
        int rem = task - grp * 384;
        int pa  = grp >> 1, ab = grp & 1;
        int r   = rem / 6, c4 = (rem - r * 6) * 4;
        const float* V = pa ? g_Vy : g_Vx;
        float4 v4 = *(const float4*)(V + ((size_t)bz * SEQ + (ab ? q0 : p0) + r) * NPOS + c4);
        *(float4*)&sm.V[pa][ab][r * KPAD + c4] = v4;
    }
    // ---- Norms: direct global load (precomputed by cope) ----
    for (int o = t; o < 256; o += 128) {
        int pa = o >> 7, ab = (o >> 6) & 1, r = o & 63;
        nrm[pa][ab][r] = g_Nrm[pa][bz * SEQ + (ab ? q0 : p0) + r];
    }
    __syncthreads();

    float wxv = *wxp;
    int rl = lane >> 2;          // 0..7
    int cg = lane & 3;           // 0..3
    int rowA = 16 * w + rl;

    float res[8][4];

    #pragma unroll 1
    for (int pa = 1; pa >= 0; pa--) {
        // Hoisted base pointers: all frag accesses become base[const]
        const float* arow0 = sm.V[pa][0] + rowA * KPAD + cg;
        const float* arow1 = arow0 + 8 * KPAD;
        const float* bbase = sm.V[pa][1] + rl * KPAD + cg;

        float acc[8][4];
        #pragma unroll
        for (int nt = 0; nt < 8; nt++)
            #pragma unroll
            for (int e = 0; e < 4; e++) acc[nt][e] = 0.0f;

        #pragma unroll
        for (int ks = 0; ks < 3; ks++) {
            uint32_t a[4];
            a[0] = __float_as_uint(arow0[8 * ks]);
            a[1] = __float_as_uint(arow1[8 * ks]);
            a[2] = __float_as_uint(arow0[8 * ks + 4]);
            a[3] = __float_as_uint(arow1[8 * ks + 4]);
            #pragma unroll
            for (int nt = 0; nt < 8; nt++) {
                uint32_t b0 = __float_as_uint(bbase[nt * 8 * KPAD + 8 * ks]);
                uint32_t b1 = __float_as_uint(bbase[nt * 8 * KPAD + 8 * ks + 4]);
                mma_tf32(acc[nt], a, b0, b1);
            }
        }

        float na0 = nrm[pa][0][rowA];
        float na1 = nrm[pa][0][rowA + 8];
        if (pa == 1) {
            float scale = 1.0f - wxv;
            #pragma unroll
            for (int nt = 0; nt < 8; nt++) {
                int c = 8 * nt + 2 * cg;
                float nb0 = nrm[1][1][c], nb1 = nrm[1][1][c + 1];
                res[nt][0] = scale * fsqrt_approx(fmaxf(fmaf(-2.0f, acc[nt][0], na0 + nb0), 0.0f));
                res[nt][1] = scale * fsqrt_approx(fmaxf(fmaf(-2.0f, acc[nt][1], na0 + nb1), 0.0f));
                res[nt][2] = scale * fsqrt_approx(fmaxf(fmaf(-2.0f, acc[nt][2], na1 + nb0), 0.0f));
                res[nt][3] = scale * fsqrt_approx(fmaxf(fmaf(-2.0f, acc[nt][3], na1 + nb1), 0.0f));
            }
        } else {
            float scale = wxv;
            #pragma unroll
            for (int nt = 0; nt < 8; nt++) {
                int c = 8 * nt + 2 * cg;
                float nb0 = nrm[0][1][c], nb1 = nrm[0][1][c + 1];
                float f0 = fmaf(scale, fsqrt_approx(fmaxf(fmaf(-2.0f, acc[nt][0], na0 + nb0), 0.0f)), res[nt][0]);
                float f1 = fmaf(scale, fsqrt_approx(fmaxf(fmaf(-2.0f, acc[nt][1], na0 + nb1), 0.0f)), res[nt][1]);
                float f2v = fmaf(scale, fsqrt_approx(fmaxf(fmaf(-2.0f, acc[nt][2], na1 + nb0), 0.0f)), res[nt][2]);
                float f3 = fmaf(scale, fsqrt_approx(fmaxf(fmaf(-2.0f, acc[nt][3], na1 + nb1), 0.0f)), res[nt][3]);
                if (p0 + rowA     == q0 + c)     f0 = 0.0f;
                if (p0 + rowA     == q0 + c + 1) f1 = 0.0f;
                if (p0 + rowA + 8 == q0 + c)     f2v = 0.0f;
                if (p0 + rowA + 8 == q0 + c + 1) f3 = 0.0f;
                res[nt][0] = f0; res[nt][1] = f1; res[nt][2] = f2v; res[nt][3] = f3;
            }
        }
    }
    __syncthreads();   // all V reads complete before T overlays

    // ---- Stage to T (overlay) ----
    {
        int c0 = 2 * cg;
        #pragma unroll
        for (int nt = 0; nt < 8; nt++) {
            int c = 8 * nt + c0;
            sm.T[rowA * 65 + c]           = res[nt][0];
            sm.T[rowA * 65 + c + 1]       = res[nt][1];
            sm.T[(rowA + 8) * 65 + c]     = res[nt][2];
            sm.T[(rowA + 8) * 65 + c + 1] = res[nt][3];
        }
    }
    __syncthreads();

    // ---- Primary tile: coalesced float4 writes ----
    for (int idx = t; idx < 1024; idx += 128) {
        int r = idx >> 4, c = (idx & 15) * 4;
        const float* xr = &sm.T[r * 65 + c];
        float4 v = make_float4(xr[0], xr[1], xr[2], xr[3]);
        *(float4*)(out + ((size_t)bz * SEQ + (p0 + r)) * SEQ + q0 + c) = v;
    }

    // ---- Mirror tile for off-diagonal pairs ----
    if (ti != tj) {
        for (int idx = t; idx < 1024; idx += 128) {
            int r = idx >> 4, c = (idx & 15) * 4;
            float4 v = make_float4(sm.T[(c + 0) * 65 + r],
                                   sm.T[(c + 1) * 65 + r],
                                   sm.T[(c + 2) * 65 + r],
                                   sm.T[(c + 3) * 65 + r]);
            *(float4*)(out + ((size_t)bz * SEQ + (q0 + r)) * SEQ + p0 + c) = v;
        }
    }
}

// ---------------------------------------------------------------------------
extern "C" void kernel_launch(void* const* d_in, const int* in_sizes, int n_in,
                              void* d_out, int out_size) {
    const float* query = (const float*)d_in[0];
    const float* attn  = (const float*)d_in[1];
    const float* pex   = (const float*)d_in[2];
    const float* pey   = (const float*)d_in[3];
    const float* wx    = (const float*)d_in[4];
    float* out = (float*)d_out;

    cope_kernel<<<2304, 512>>>(query, attn, pex, pey);

    dim3 dgrid(45, BATCH);
    dist_kernel<<<dgrid, 128>>>(wx, out);
}

// round 16
// speedup vs baseline: 1.1697x; 1.1697x over previous
#include <cuda_runtime.h>
#include <cstdint>

#define NB      8
#define NHEADS  12
#define HH      24
#define SEQ     576
#define DIM     64
#define NPOS    24
#define BATCH   96
#define KPAD    28          // row stride (words): 16B-aligned; frag reads conflict-free

// Scratch: pe_x_flat / pe_y_flat  [BATCH][SEQ][NPOS]
__device__ __align__(16) float g_Vx[BATCH * SEQ * NPOS];
__device__ __align__(16) float g_Vy[BATCH * SEQ * NPOS];

__device__ __forceinline__ float sigmoidf_(float x) {
    return 1.0f / (1.0f + __expf(-x));
}

__device__ __forceinline__ unsigned long long fma2(unsigned long long a,
                                                   unsigned long long b,
                                                   unsigned long long c) {
    unsigned long long d;
    asm("fma.rn.f32x2 %0, %1, %2, %3;" : "=l"(d) : "l"(a), "l"(b), "l"(c));
    return d;
}

__device__ __forceinline__ unsigned long long pack2(float lo, float hi) {
    unsigned long long r;
    asm("mov.b64 %0, {%1, %2};" : "=l"(r) : "f"(lo), "f"(hi));
    return r;
}

__device__ __forceinline__ float fsqrt_approx(float x) {
    float r;
    asm("sqrt.approx.f32 %0, %1;" : "=f"(r) : "f"(x));
    return r;
}

__device__ __forceinline__ uint32_t f2tf32(float v) {
    uint32_t r;
    asm("cvt.rna.tf32.f32 %0, %1;" : "=r"(r) : "f"(v));
    return r;
}

__device__ __forceinline__ void mma_tf32(float* c, const uint32_t* a, uint32_t b0, uint32_t b1) {
    asm volatile(
        "mma.sync.aligned.m16n8k8.row.col.f32.tf32.tf32.f32 "
        "{%0,%1,%2,%3}, {%4,%5,%6,%7}, {%8,%9}, {%0,%1,%2,%3};"
        : "+f"(c[0]), "+f"(c[1]), "+f"(c[2]), "+f"(c[3])
        : "r"(a[0]), "r"(a[1]), "r"(a[2]), "r"(a[3]), "r"(b0), "r"(b1));
}

// ---------------------------------------------------------------------------
// Kernel 1: fused CoPE (EXACT R12 form — measured 47.2 us).
// ---------------------------------------------------------------------------
__global__ void __launch_bounds__(512) cope_kernel(
    const float* __restrict__ query,      // [8,12,576,64]
    const float* __restrict__ attn,       // [8,12,576,576]
    const float* __restrict__ pex,        // [64,24]
    const float* __restrict__ pey)        // [64,24]
{
    __shared__ __align__(16) float q_s[2][HH * 68];
    __shared__ __align__(16) float pe_s[2][DIM * NPOS];
    __shared__ __align__(8)  float li[2][HH * 26];

    int t    = threadIdx.x;
    int path = t >> 8;
    int tp   = t & 255;

    int id   = blockIdx.x;
    int n    = id / 12;
    int m    = id % 12;
    int b_a  = id / 288;
    int hd_a = (id / 24) % 12;
    int r_a  = id % 24;
    int b_q  = n / 24;
    int s_q  = n % 24;

    {
        const float4* pe4 = (const float4*)(path ? pey : pex);
        float4* d4 = (float4*)pe_s[path];
        for (int idx = tp; idx < DIM * NPOS / 4; idx += 256)
            d4[idx] = pe4[idx];
    }

    if (!path) {
        const float4* qb = (const float4*)(query + (((size_t)(b_q * 12 + m)) * SEQ + s_q * 24) * DIM);
        for (int idx = tp; idx < HH * DIM / 4; idx += 256) {
            int rr = idx >> 4, c4 = (idx & 15) * 4;
            *(float4*)&q_s[0][rr * 68 + c4] = qb[idx];
        }
    } else {
        const float* qb = query + (((size_t)(b_q * 12 + m)) * SEQ + s_q) * DIM;
        for (int idx = tp; idx < HH * DIM / 4; idx += 256) {
            int rr = idx >> 4, c4 = (idx & 15) * 4;
            *(float4*)&q_s[1][rr * 68 + c4] = *(const float4*)(qb + (size_t)rr * (24 * DIM) + c4);
        }
    }
    __syncthreads();

    for (int o = t; o < 2 * HH * 12; o += 512) {
        int pa  = (o >= 288) ? 1 : 0;
        int rem = o - pa * 288;
        int j   = rem / 12;
        int pp  = rem - j * 12;
        const float4* qr4 = (const float4*)&q_s[pa][j * 68];
        const float*  pr  = pe_s[pa] + 2 * pp;
        unsigned long long acc = 0ull;
        #pragma unroll
        for (int dq = 0; dq < 16; dq++) {
            float4 q4 = qr4[dq];
            float2 v0 = *(const float2*)(pr + (4 * dq + 0) * NPOS);
            float2 v1 = *(const float2*)(pr + (4 * dq + 1) * NPOS);
            float2 v2 = *(const float2*)(pr + (4 * dq + 2) * NPOS);
            float2 v3 = *(const float2*)(pr + (4 * dq + 3) * NPOS);
            acc = fma2(pack2(q4.x, q4.x), pack2(v0.x, v0.y), acc);
            acc = fma2(pack2(q4.y, q4.y), pack2(v1.x, v1.y), acc);
            acc = fma2(pack2(q4.z, q4.z), pack2(v2.x, v2.y), acc);
            acc = fma2(pack2(q4.w, q4.w), pack2(v3.x, v3.y), acc);
        }
        *(float2*)(&li[pa][j * 26 + 2 * pp]) = *(float2*)&acc;
    }
    __syncthreads();

    int w    = (t >> 5) & 7;
    int lane = t & 31;
    int bh   = b_q * 12 + m;
    for (int j = w; j < HH; j += 8) {
        const float* arow;
        int astride;
        float* dst;
        if (!path) {
            arow = attn + (((size_t)(b_a * 12 + hd_a)) * SEQ + (size_t)(r_a * 24 + j)) * SEQ
                        + (size_t)(r_a * 24);
            astride = 1;
            dst = g_Vx + ((size_t)bh * SEQ + (size_t)(s_q * 24 + j)) * NPOS;
        } else {
            arow = attn + (((size_t)(b_a * 12 + hd_a)) * SEQ + (size_t)(j * 24 + r_a)) * SEQ
                        + (size_t)r_a;
            astride = 24;
            dst = g_Vy + ((size_t)bh * SEQ + (size_t)(j * 24 + s_q)) * NPOS;
        }
        float v = 0.0f;
        if (lane < NPOS)
            v = sigmoidf_(arow[lane * astride]);
        #pragma unroll
        for (int d = 1; d < 32; d <<= 1) {
            float tv = __shfl_down_sync(0xffffffffu, v, d);
            if (lane + d < NPOS) v += tv;
        }
        if (lane < NPOS) {
            float pp = fminf(v, (float)(NPOS - 1));
            float pf = floorf(pp);
            int   ifl = (int)pf;
            int   ic  = (int)ceilf(pp);
            float wq  = pp - pf;
            float val = li[path][j * 26 + ic] * wq + li[path][j * 26 + ifl] * (1.0f - wq);
            dst[lane] = val;
        }
    }
}

// ---------------------------------------------------------------------------
// Kernel 2: fused double-cdist + mix via tf32 mma.
// Load phase: division-free (row = t>>1, half = t&1), cvt in registers,
// partner-shuffle row norms (NO separate norm pass, no norm LDS).
// Mainloop: hoisted base pointers, immediate-offset scalar frag LDS
// (conflict-free: bank = 28*(lane>>2)+(lane&3) mod 32 covers all banks).
// ---------------------------------------------------------------------------
union DistSm {
    float V[2][2][64 * KPAD];   // [path][A=0/B=1][row][k], tf32-truncated
    float T[64 * 65];
};

__global__ void __launch_bounds__(128) dist_kernel(
    const float* __restrict__ wxp,
    float* __restrict__ out)
{
    __shared__ __align__(16) DistSm sm;
    __shared__ float nrm[2][2][64];

    int bz = blockIdx.y;
    int u = blockIdx.x;
    int ti = 0;
    #pragma unroll 1
    while (u >= (9 - ti)) { u -= (9 - ti); ti++; }
    int tj = ti + u;
    int p0 = ti * 64;
    int q0 = tj * 64;

    int t    = threadIdx.x;     // 0..127
    int w    = t >> 5;          // warp id = m-strip
    int lane = t & 31;

    // ---- Load + cvt + partner-shfl norm: row r=t>>1, half h=t&1 ----
    {
        int rr = t >> 1;
        int hf = t & 1;
        #pragma unroll
        for (int g = 0; g < 4; g++) {
            int pa = g >> 1, ab = g & 1;
            const float* V = pa ? g_Vy : g_Vx;
            const float* src = V + ((size_t)bz * SEQ + (ab ? q0 : p0) + rr) * NPOS + hf * 4;
            float* dstrow = &sm.V[pa][ab][rr * KPAD + hf * 4];
            float np = 0.0f;
            #pragma unroll
            for (int i = 0; i < 3; i++) {
                float4 v4 = *(const float4*)(src + 8 * i);
                float4 tv;
                tv.x = __uint_as_float(f2tf32(v4.x));
                tv.y = __uint_as_float(f2tf32(v4.y));
                tv.z = __uint_as_float(f2tf32(v4.z));
                tv.w = __uint_as_float(f2tf32(v4.w));
                *(float4*)(dstrow + 8 * i) = tv;
                np = fmaf(tv.x, tv.x, np);
                np = fmaf(tv.y, tv.y, np);
                np = fmaf(tv.z, tv.z, np);
                np = fmaf(tv.w, tv.w, np);
            }
            np += __shfl_xor_sync(0xffffffffu, np, 1);
            if (!hf) nrm[pa][ab][rr] = np;
        }
    }
    __syncthreads();

    float wxv = *wxp;
    int rl = lane >> 2;          // 0..7
    int cg = lane & 3;           // 0..3
    int rowA = 16 * w + rl;

    float res[8][4];

    #pragma unroll 1
    for (int pa = 1; pa >= 0; pa--) {
        // Hoisted base pointers: all frag accesses become base[const]
        const float* arow0 = sm.V[pa][0] + rowA * KPAD + cg;
        const float* arow1 = arow0 + 8 * KPAD;
        const float* bbase = sm.V[pa][1] + rl * KPAD + cg;

        float acc[8][4];
        #pragma unroll
        for (int nt = 0; nt < 8; nt++)
            #pragma unroll
            for (int e = 0; e < 4; e++) acc[nt][e] = 0.0f;

        #pragma unroll
        for (int ks = 0; ks < 3; ks++) {
            uint32_t a[4];
            a[0] = __float_as_uint(arow0[8 * ks]);
            a[1] = __float_as_uint(arow1[8 * ks]);
            a[2] = __float_as_uint(arow0[8 * ks + 4]);
            a[3] = __float_as_uint(arow1[8 * ks + 4]);
            #pragma unroll
            for (int nt = 0; nt < 8; nt++) {
                uint32_t b0 = __float_as_uint(bbase[nt * 8 * KPAD + 8 * ks]);
                uint32_t b1 = __float_as_uint(bbase[nt * 8 * KPAD + 8 * ks + 4]);
                mma_tf32(acc[nt], a, b0, b1);
            }
        }

        float na0 = nrm[pa][0][rowA];
        float na1 = nrm[pa][0][rowA + 8];
        if (pa == 1) {
            float scale = 1.0f - wxv;
            #pragma unroll
            for (int nt = 0; nt < 8; nt++) {
                int c = 8 * nt + 2 * cg;
                float nb0 = nrm[1][1][c], nb1 = nrm[1][1][c + 1];
                res[nt][0] = scale * fsqrt_approx(fmaxf(fmaf(-2.0f, acc[nt][0], na0 + nb0), 0.0f));
                res[nt][1] = scale * fsqrt_approx(fmaxf(fmaf(-2.0f, acc[nt][1], na0 + nb1), 0.0f));
                res[nt][2] = scale * fsqrt_approx(fmaxf(fmaf(-2.0f, acc[nt][2], na1 + nb0), 0.0f));
                res[nt][3] = scale * fsqrt_approx(fmaxf(fmaf(-2.0f, acc[nt][3], na1 + nb1), 0.0f));
            }
        } else {
            float scale = wxv;
            #pragma unroll
            for (int nt = 0; nt < 8; nt++) {
                int c = 8 * nt + 2 * cg;
                float nb0 = nrm[0][1][c], nb1 = nrm[0][1][c + 1];
                float f0 = fmaf(scale, fsqrt_approx(fmaxf(fmaf(-2.0f, acc[nt][0], na0 + nb0), 0.0f)), res[nt][0]);
                float f1 = fmaf(scale, fsqrt_approx(fmaxf(fmaf(-2.0f, acc[nt][1], na0 + nb1), 0.0f)), res[nt][1]);
                float f2v = fmaf(scale, fsqrt_approx(fmaxf(fmaf(-2.0f, acc[nt][2], na1 + nb0), 0.0f)), res[nt][2]);
                float f3 = fmaf(scale, fsqrt_approx(fmaxf(fmaf(-2.0f, acc[nt][3], na1 + nb1), 0.0f)), res[nt][3]);
                if (p0 + rowA     == q0 + c)     f0 = 0.0f;
                if (p0 + rowA     == q0 + c + 1) f1 = 0.0f;
                if (p0 + rowA + 8 == q0 + c)     f2v = 0.0f;
                if (p0 + rowA + 8 == q0 + c + 1) f3 = 0.0f;
                res[nt][0] = f0; res[nt][1] = f1; res[nt][2] = f2v; res[nt][3] = f3;
            }
        }
    }
    __syncthreads();   // all V reads complete before T overlays

    // ---- Stage to T (overlay) ----
    {
        int c0 = 2 * cg;
        #pragma unroll
        for (int nt = 0; nt < 8; nt++) {
            int c = 8 * nt + c0;
            sm.T[rowA * 65 + c]           = res[nt][0];
            sm.T[rowA * 65 + c + 1]       = res[nt][1];
            sm.T[(rowA + 8) * 65 + c]     = res[nt][2];
            sm.T[(rowA + 8) * 65 + c + 1] = res[nt][3];
        }
    }
    __syncthreads();

    // ---- Primary tile: coalesced float4 writes ----
    for (int idx = t; idx < 1024; idx += 128) {
        int r = idx >> 4, c = (idx & 15) * 4;
        const float* xr = &sm.T[r * 65 + c];
        float4 v = make_float4(xr[0], xr[1], xr[2], xr[3]);
        *(float4*)(out + ((size_t)bz * SEQ + (p0 + r)) * SEQ + q0 + c) = v;
    }

    // ---- Mirror tile for off-diagonal pairs ----
    if (ti != tj) {
        for (int idx = t; idx < 1024; idx += 128) {
            int r = idx >> 4, c = (idx & 15) * 4;
            float4 v = make_float4(sm.T[(c + 0) * 65 + r],
                                   sm.T[(c + 1) * 65 + r],
                                   sm.T[(c + 2) * 65 + r],
                                   sm.T[(c + 3) * 65 + r]);
            *(float4*)(out + ((size_t)bz * SEQ + (q0 + r)) * SEQ + p0 + c) = v;
        }
    }
}

// ---------------------------------------------------------------------------
extern "C" void kernel_launch(void* const* d_in, const int* in_sizes, int n_in,
                              void* d_out, int out_size) {
    const float* query = (const float*)d_in[0];
    const float* attn  = (const float*)d_in[1];
    const float* pex   = (const float*)d_in[2];
    const float* pey   = (const float*)d_in[3];
    const float* wx    = (const float*)d_in[4];
    float* out = (float*)d_out;

    cope_kernel<<<2304, 512>>>(query, attn, pex, pey);

    dim3 dgrid(45, BATCH);
    dist_kernel<<<dgrid, 128>>>(wx, out);
}